// round 14
// baseline (speedup 1.0000x reference)
#include <cuda_runtime.h>
#include <cuda_fp16.h>
#include <cstdint>

// ============================================================================
// Problem constants
// ============================================================================
#define TOK   16384      // 4 * 4096 tokens
#define F     2048       // in/out features

// ============================================================================
// Device scratch (static globals — allocation-free per harness rules)
// ============================================================================
__device__ __half    g_W[F * F];       // W_eff fp16 (8.4 MB)
__device__ __half    g_X[TOK * F];     // x fp16 (67 MB)
__device__ unsigned  g_cnt[TOK / 128]; // per-panel conversion counters (128)

// ============================================================================
// Helpers
// ============================================================================
__device__ __forceinline__ uint32_t smem_to_u32(const void* p) {
    uint32_t a;
    asm("{ .reg .u64 t; cvta.to.shared.u64 t, %1; cvt.u32.u64 %0, t; }"
        : "=r"(a) : "l"(p));
    return a;
}

__device__ __forceinline__ unsigned ld_acquire_gpu(const unsigned* p) {
    unsigned v;
    asm volatile("ld.acquire.gpu.global.b32 %0, [%1];" : "=r"(v) : "l"(p));
    return v;
}

// ============================================================================
// Fold kernel v3: W_eff = stage2 ∘ shuffle ∘ mix ∘ stage1, oo-split for
// wave packing. 2048 blocks; block b -> (ot = b>>6, g = (b&63)>>1, h = b&1).
// Each block produces the 32-row oo-half [h*32, h*32+32) of W block (ot, g):
//   mixP[c][dd] = mix_w[ot*64+c, sig(g*64+dd)]  (pair-gather: one float2
//     yields dd=k and dd=k+32 since sig(g*64+dd) = 64*(dd&31) + 2g + (dd>>5))
//   M[oo][dd]   = sum_c stage2[ot*64+c, oo] * mixP[c][dd]     (oo in half)
//   W[ot*64+oo, g*64+c2] = sum_dd M[oo][dd] * stage1[g*64+c2, dd]
// smem ~25 KB -> 8 CTAs/SM (thread-capped), ~1.7 waves of half-size blocks.
// ============================================================================
__global__ __launch_bounds__(256)
void fold_kernel(const float* __restrict__ stage1,
                 const float* __restrict__ stage2,
                 const float* __restrict__ mix_w) {
    __shared__ float bufP[64 * 65];   // A/B: mixP [c][dd] s65 ; C/D: stage1 [c2][dd] s65
    __shared__ float bufQ[64 * 33];   // A/B: stage2-half [c][o2] s33 ; C/D: M [o2][dd] s65 (32 rows)

    const int b = blockIdx.x;
    const int tid = threadIdx.x;
    const int ot = b >> 6, g = (b & 63) >> 1, h = b & 1;

    if (b == 0 && tid < TOK / 128) g_cnt[tid] = 0;   // reset panel counters

    // ---- Phase A: stage2 half-block [c][o2] + pair-gathered mix_w [c][dd] ----
    for (int i = tid; i < 64 * 32; i += 256) {
        int c = i >> 5, o2 = i & 31;
        bufQ[c * 33 + o2] = stage2[(ot * 64 + c) * 64 + h * 32 + o2];
    }
#pragma unroll
    for (int it = 0; it < 8; it++) {
        int i = tid + it * 256;                // 0..2047 -> (c, k)
        int c = i >> 5, k = i & 31;
        float2 v = *(const float2*)(mix_w +
                     (size_t)(ot * 64 + c) * F + 64 * k + 2 * g);
        bufP[c * 65 + k]      = v.x;           // mixP[c][k]
        bufP[c * 65 + k + 32] = v.y;           // mixP[c][k+32]
    }
    __syncthreads();

    // ---- Phase B: M half. thread = (j = dd, q), owns rows o2 = q*8..q*8+7 ----
    const int j = tid & 63, q = tid >> 6;
    float macc[8];
#pragma unroll
    for (int k = 0; k < 8; k++) macc[k] = 0.0f;
    for (int c = 0; c < 64; c++) {
        float mx = bufP[c * 65 + j];
#pragma unroll
        for (int k = 0; k < 8; k++) macc[k] += bufQ[c * 33 + q * 8 + k] * mx;
    }
    __syncthreads();

    // ---- Phase C: M [o2][dd] s65 into bufQ (32 rows); stage1 into bufP ----
#pragma unroll
    for (int k = 0; k < 8; k++) bufQ[(q * 8 + k) * 65 + j] = macc[k];
    for (int i = tid; i < 64 * 64; i += 256) {
        int c2 = i >> 6, dd = i & 63;
        bufP[c2 * 65 + dd] = stage1[(g * 64 + c2) * 64 + dd];
    }
    __syncthreads();

    // ---- Phase D: W[o2][c2] = sum_dd M[o2][dd] * stage1[c2][dd] ----
    const int c2 = j;
    float wacc[8];
#pragma unroll
    for (int k = 0; k < 8; k++) wacc[k] = 0.0f;
    for (int dd = 0; dd < 64; dd++) {
        float w1 = bufP[c2 * 65 + dd];
#pragma unroll
        for (int k = 0; k < 8; k++) wacc[k] += bufQ[(q * 8 + k) * 65 + dd] * w1;
    }
#pragma unroll
    for (int k = 0; k < 8; k++)
        g_W[(size_t)(ot * 64 + h * 32 + q * 8 + k) * F + g * 64 + c2] =
            __float2half_rn(wacc[k]);
}

// ============================================================================
// Main GEMM: out[t, o] = sum_k x[t,k] * W[o,k]   (fp16 inputs, fp32 accum)
// Inline distributed x->fp16 conversion + panel rendezvous (R7/R11 proven).
// CTA tile 128x128, K chunk 64, 3-stage cp.async pipeline, 8 warps (2x4).
// ============================================================================
static constexpr int BM = 128, BN = 128, BK = 64, STAGES = 3;
static constexpr int A_STAGE_BYTES = BM * BK * 2;               // 16384
static constexpr int STAGE_BYTES   = (BM + BN) * BK * 2;        // 32768
static constexpr int SMEM_BYTES    = STAGES * STAGE_BYTES;      // 98304

__global__ __launch_bounds__(256, 2)
void gemm_kernel(const float* __restrict__ x, float* __restrict__ out) {
    extern __shared__ char smem[];
    const uint32_t sbase = smem_to_u32(smem);
    const int tid  = threadIdx.x;
    const int lane = tid & 31, wid = tid >> 5;
    const int m0 = blockIdx.y * BM;
    const int n0 = blockIdx.x * BN;
    const int wm = (wid >> 2) * 64;     // warp m-origin in tile
    const int wn = (wid & 3) * 32;      // warp n-origin in tile

    // ---- distributed conversion: blockIdx.x owns 8 rows of panel m0 ----
    {
        const size_t base = ((size_t)m0 + (size_t)blockIdx.x * 8) * F;
#pragma unroll 8
        for (int it = 0; it < 16; it++) {
            size_t off = base + (size_t)it * 1024 + (size_t)tid * 4;
            float4 v = *(const float4*)(x + off);
            __half2 h0 = __floats2half2_rn(v.x, v.y);
            __half2 h1 = __floats2half2_rn(v.z, v.w);
            uint2 w;
            w.x = *(uint32_t*)&h0; w.y = *(uint32_t*)&h1;
            *(uint2*)(g_X + off) = w;
        }
        __threadfence();
        __syncthreads();
        if (tid == 0) {
            atomicAdd(&g_cnt[blockIdx.y], 1u);
            while (ld_acquire_gpu(&g_cnt[blockIdx.y]) < 16u) { }
        }
        __syncthreads();
    }

    // ---- cp.async geometry: 4 x 16B per thread per operand per stage ----
    uint32_t dst_off[4];
    size_t   srcA[4], srcB[4];
#pragma unroll
    for (int i = 0; i < 4; i++) {
        int u = tid + 256 * i;                // 0..1023
        int row = u >> 3, seg = u & 7;        // 128 rows x 8 segs of 16B
        dst_off[i] = (uint32_t)(row * 128 + ((seg ^ (row & 7)) * 16));
        srcA[i] = (size_t)(m0 + row) * F + seg * 8;
        srcB[i] = (size_t)(n0 + row) * F + seg * 8;
    }
    const __half* gA = g_X;
    const __half* gB = g_W;

    auto issue_stage = [&](int kc, int st) {
        uint32_t sA = sbase + st * STAGE_BYTES;
        uint32_t sB = sA + A_STAGE_BYTES;
        const __half* pa = gA + (size_t)kc * BK;
        const __half* pb = gB + (size_t)kc * BK;
#pragma unroll
        for (int i = 0; i < 4; i++) {
            asm volatile("cp.async.cg.shared.global [%0], [%1], 16;"
                         :: "r"(sA + dst_off[i]), "l"(pa + srcA[i]) : "memory");
            asm volatile("cp.async.cg.shared.global [%0], [%1], 16;"
                         :: "r"(sB + dst_off[i]), "l"(pb + srcB[i]) : "memory");
        }
    };

    // ---- ldmatrix per-lane addressing ----
    const uint32_t aRow = (uint32_t)(wm + (lane & 15));
    const uint32_t bRow = (uint32_t)(wn + ((lane & 7) | ((lane & 16) >> 1)));
    uint32_t xsA[4], xsB[4];
#pragma unroll
    for (int ks = 0; ks < 4; ks++) {
        xsA[ks] = (uint32_t)(((ks * 2 + (lane >> 4)) ^ (lane & 7)) * 16);
        xsB[ks] = (uint32_t)(((ks * 2 + ((lane >> 3) & 1)) ^ (lane & 7)) * 16);
    }
    const uint32_t aBase = aRow * 128u;
    const uint32_t bBase = bRow * 128u;

    float acc[4][4][4];
#pragma unroll
    for (int fm = 0; fm < 4; fm++)
#pragma unroll
        for (int fn = 0; fn < 4; fn++)
#pragma unroll
            for (int k = 0; k < 4; k++) acc[fm][fn][k] = 0.0f;

    auto compute_stage = [&](int st) {
        uint32_t sA = sbase + st * STAGE_BYTES + aBase;
        uint32_t sB = sbase + st * STAGE_BYTES + A_STAGE_BYTES + bBase;
#pragma unroll
        for (int ks = 0; ks < 4; ks++) {
            uint32_t a[4][4], b[8];
#pragma unroll
            for (int fm = 0; fm < 4; fm++) {
                uint32_t addr = sA + (uint32_t)(fm * 2048) + xsA[ks];
                asm volatile(
                    "ldmatrix.sync.aligned.m8n8.x4.shared.b16 {%0,%1,%2,%3}, [%4];"
                    : "=r"(a[fm][0]), "=r"(a[fm][1]), "=r"(a[fm][2]), "=r"(a[fm][3])
                    : "r"(addr));
            }
#pragma unroll
            for (int p = 0; p < 2; p++) {
                uint32_t addr = sB + (uint32_t)(p * 2048) + xsB[ks];
                asm volatile(
                    "ldmatrix.sync.aligned.m8n8.x4.shared.b16 {%0,%1,%2,%3}, [%4];"
                    : "=r"(b[p*4+0]), "=r"(b[p*4+1]), "=r"(b[p*4+2]), "=r"(b[p*4+3])
                    : "r"(addr));
            }
#pragma unroll
            for (int fm = 0; fm < 4; fm++) {
#pragma unroll
                for (int fn = 0; fn < 4; fn++) {
                    uint32_t b0 = b[(fn >> 1) * 4 + (fn & 1) * 2];
                    uint32_t b1 = b[(fn >> 1) * 4 + (fn & 1) * 2 + 1];
                    asm volatile(
                        "mma.sync.aligned.m16n8k16.row.col.f32.f16.f16.f32 "
                        "{%0,%1,%2,%3}, {%4,%5,%6,%7}, {%8,%9}, {%0,%1,%2,%3};"
                        : "+f"(acc[fm][fn][0]), "+f"(acc[fm][fn][1]),
                          "+f"(acc[fm][fn][2]), "+f"(acc[fm][fn][3])
                        : "r"(a[fm][0]), "r"(a[fm][1]), "r"(a[fm][2]), "r"(a[fm][3]),
                          "r"(b0), "r"(b1));
                }
            }
        }
    };

    // ---- pipeline ----
    issue_stage(0, 0);
    asm volatile("cp.async.commit_group;" ::: "memory");
    issue_stage(1, 1);
    asm volatile("cp.async.commit_group;" ::: "memory");

    const int NCHUNK = F / BK;   // 32
    for (int kc = 0; kc < NCHUNK; kc++) {
        asm volatile("cp.async.wait_group 1;" ::: "memory");
        __syncthreads();
        if (kc + 2 < NCHUNK) {
            int nxt = kc + 2;
            issue_stage(nxt, nxt % STAGES);
        }
        asm volatile("cp.async.commit_group;" ::: "memory");
        compute_stage(kc % STAGES);
    }

    // ---- epilogue: direct fp32 stores ----
#pragma unroll
    for (int fm = 0; fm < 4; fm++) {
#pragma unroll
        for (int fn = 0; fn < 4; fn++) {
            int r = m0 + wm + fm * 16 + (lane >> 2);
            int c = n0 + wn + fn * 8 + (lane & 3) * 2;
            float2 v0 = make_float2(acc[fm][fn][0], acc[fm][fn][1]);
            float2 v1 = make_float2(acc[fm][fn][2], acc[fm][fn][3]);
            *(float2*)(out + (size_t)r * F + c)       = v0;
            *(float2*)(out + (size_t)(r + 8) * F + c) = v1;
        }
    }
}

// ============================================================================
// Launch
// ============================================================================
extern "C" void kernel_launch(void* const* d_in, const int* in_sizes, int n_in,
                              void* d_out, int out_size) {
    const float* x      = (const float*)d_in[0];
    const float* stage1 = (const float*)d_in[1];
    const float* stage2 = (const float*)d_in[2];
    const float* mix_w  = (const float*)d_in[3];
    float* out = (float*)d_out;

    cudaFuncSetAttribute(gemm_kernel,
                         cudaFuncAttributeMaxDynamicSharedMemorySize, SMEM_BYTES);

    fold_kernel<<<2048, 256>>>(stage1, stage2, mix_w);
    gemm_kernel<<<dim3(F / BN, TOK / BM), 256, SMEM_BYTES>>>(x, out);
}

// round 15
// speedup vs baseline: 1.0794x; 1.0794x over previous
#include <cuda_runtime.h>
#include <cuda_fp16.h>
#include <cstdint>

// ============================================================================
// Problem constants
// ============================================================================
#define TOK   16384      // 4 * 4096 tokens
#define F     2048       // in/out features

// ============================================================================
// Device scratch (static globals — allocation-free per harness rules)
// ============================================================================
__device__ __half    g_W[F * F];       // W_eff fp16 (8.4 MB)
__device__ __half    g_X[TOK * F];     // x fp16 (67 MB)
__device__ unsigned  g_cnt[TOK / 128]; // per-panel conversion counters (128)

// ============================================================================
// Helpers
// ============================================================================
__device__ __forceinline__ uint32_t smem_to_u32(const void* p) {
    uint32_t a;
    asm("{ .reg .u64 t; cvta.to.shared.u64 t, %1; cvt.u32.u64 %0, t; }"
        : "=r"(a) : "l"(p));
    return a;
}

__device__ __forceinline__ unsigned ld_acquire_gpu(const unsigned* p) {
    unsigned v;
    asm volatile("ld.acquire.gpu.global.b32 %0, [%1];" : "=r"(v) : "l"(p));
    return v;
}

// ============================================================================
// Fold kernel v4 — TENSOR-CORE fold. Per block (ot = b>>5, g = b&31):
//   M[oo][dd] = sum_c stage2[ot*64+c][oo] * mixP[c][dd]       (HMMA GEMM 1)
//   W[ot*64+oo][g*64+c2] = sum_dd M[oo][dd] * stage1[g*64+c2][dd]  (HMMA GEMM 2)
// Operands stored PRE-TRANSPOSED in fp16 smem so both GEMMs are mma row.col:
//   s2T[oo][c] = stage2[ot*64+c][oo],  mxT[dd][c] = mixP[c][dd]
//   (pair-gather: sig(g*64+dd) = 64*(dd&31) + 2g + (dd>>5) -> one float2
//    yields dd=k (v.x) and dd=k+32 (v.y))
// 8 warps: warp w -> 16x32 output region (mrow = (w>>1)*16, ncol = (w&1)*32).
// Stride FS=72 halves: ldmatrix rows hit disjoint 4-bank groups (conflict-free).
// ============================================================================
#define FS 72   // fp16 smem row stride (halves)

__global__ __launch_bounds__(256)
void fold_kernel(const float* __restrict__ stage1,
                 const float* __restrict__ stage2,
                 const float* __restrict__ mix_w) {
    __shared__ __half s2T[64 * FS];   // [oo][c]   A of GEMM1
    __shared__ __half mxT[64 * FS];   // [dd][c]   B of GEMM1
    __shared__ __half s1s[64 * FS];   // [c2][dd]  B of GEMM2
    __shared__ __half mTs[64 * FS];   // [oo][dd]  M (out of GEMM1, A of GEMM2)

    const int b = blockIdx.x, tid = threadIdx.x;
    const int ot = b >> 5, g = b & 31;
    const int lane = tid & 31, w = tid >> 5;

    if (b == 0 && tid < TOK / 128) g_cnt[tid] = 0;   // reset panel counters

    // ---- loads (fp32 -> fp16, transposed where needed) ----
    for (int i = tid; i < 4096; i += 256) {
        int c = i >> 6, oo = i & 63;                 // coalesced read along oo
        s2T[oo * FS + c] = __float2half_rn(stage2[(ot * 64 + c) * 64 + oo]);
    }
#pragma unroll
    for (int it = 0; it < 8; it++) {
        int i = tid + it * 256;                      // (c, k) pair-gather
        int c = i >> 5, k = i & 31;
        float2 v = *(const float2*)(mix_w +
                     (size_t)(ot * 64 + c) * F + 64 * k + 2 * g);
        mxT[k * FS + c]        = __float2half_rn(v.x);   // dd = k
        mxT[(k + 32) * FS + c] = __float2half_rn(v.y);   // dd = k+32
    }
    for (int i = tid; i < 4096; i += 256) {
        int c2 = i >> 6, dd = i & 63;                // coalesced, no transpose
        s1s[c2 * FS + dd] = __float2half_rn(stage1[(g * 64 + c2) * 64 + dd]);
    }
    __syncthreads();

    const int mrow = (w >> 1) * 16;    // warp m-origin (oo)
    const int ncol = (w & 1) * 32;     // warp n-origin
    const uint32_t uS2 = smem_to_u32(s2T);
    const uint32_t uMx = smem_to_u32(mxT);
    const uint32_t uS1 = smem_to_u32(s1s);
    const uint32_t uMT = smem_to_u32(mTs);

    // per-lane ldmatrix row/chunk offsets (halves -> bytes at use site)
    const int aRow = mrow + (lane & 15);
    const int aChk = (lane >> 4);                    // 0/1 k-chunk
    const int bOff = (lane & 7) | ((lane & 16) >> 1);
    const int bChk = (lane >> 3) & 1;

    // one 64x64x64 GEMM phase: D[16x32] for this warp from A(base uA) x B(uB)
    auto gemm64 = [&](uint32_t uA, uint32_t uB, float acc[4][4]) {
#pragma unroll
        for (int fn = 0; fn < 4; fn++)
#pragma unroll
            for (int k = 0; k < 4; k++) acc[fn][k] = 0.0f;
#pragma unroll
        for (int ks = 0; ks < 4; ks++) {
            uint32_t a[4], bb[8];
            uint32_t aAddr = uA + (uint32_t)((aRow * FS + ks * 16 + aChk * 8) * 2);
            asm volatile(
                "ldmatrix.sync.aligned.m8n8.x4.shared.b16 {%0,%1,%2,%3}, [%4];"
                : "=r"(a[0]), "=r"(a[1]), "=r"(a[2]), "=r"(a[3]) : "r"(aAddr));
#pragma unroll
            for (int p = 0; p < 2; p++) {
                uint32_t bAddr = uB + (uint32_t)(((ncol + p * 16 + bOff) * FS
                                    + ks * 16 + bChk * 8) * 2);
                asm volatile(
                    "ldmatrix.sync.aligned.m8n8.x4.shared.b16 {%0,%1,%2,%3}, [%4];"
                    : "=r"(bb[p*4+0]), "=r"(bb[p*4+1]),
                      "=r"(bb[p*4+2]), "=r"(bb[p*4+3]) : "r"(bAddr));
            }
#pragma unroll
            for (int fn = 0; fn < 4; fn++) {
                uint32_t b0 = bb[(fn >> 1) * 4 + (fn & 1) * 2];
                uint32_t b1 = bb[(fn >> 1) * 4 + (fn & 1) * 2 + 1];
                asm volatile(
                    "mma.sync.aligned.m16n8k16.row.col.f32.f16.f16.f32 "
                    "{%0,%1,%2,%3}, {%4,%5,%6,%7}, {%8,%9}, {%0,%1,%2,%3};"
                    : "+f"(acc[fn][0]), "+f"(acc[fn][1]),
                      "+f"(acc[fn][2]), "+f"(acc[fn][3])
                    : "r"(a[0]), "r"(a[1]), "r"(a[2]), "r"(a[3]),
                      "r"(b0), "r"(b1));
            }
        }
    };

    // ---- GEMM 1: M = stage2^T x mixP ----
    float acc1[4][4];
    gemm64(uS2, uMx, acc1);

    // store M (fp16) to mTs: D lane map row=(lane>>2)(+8), col=(lane&3)*2
    {
        const int rr = mrow + (lane >> 2);
#pragma unroll
        for (int fn = 0; fn < 4; fn++) {
            const int cc = ncol + fn * 8 + (lane & 3) * 2;
            __half2 lo = __floats2half2_rn(acc1[fn][0], acc1[fn][1]);
            __half2 hi = __floats2half2_rn(acc1[fn][2], acc1[fn][3]);
            *(__half2*)(mTs + rr * FS + cc)       = lo;
            *(__half2*)(mTs + (rr + 8) * FS + cc) = hi;
        }
    }
    __syncthreads();

    // ---- GEMM 2: W = M x stage1^T ----
    float acc2[4][4];
    gemm64(uMT, uS1, acc2);

    // write W_eff fp16 to global
    {
        const int rr = ot * 64 + mrow + (lane >> 2);
#pragma unroll
        for (int fn = 0; fn < 4; fn++) {
            const int cc = g * 64 + ncol + fn * 8 + (lane & 3) * 2;
            __half2 lo = __floats2half2_rn(acc2[fn][0], acc2[fn][1]);
            __half2 hi = __floats2half2_rn(acc2[fn][2], acc2[fn][3]);
            *(__half2*)(g_W + (size_t)rr * F + cc)       = lo;
            *(__half2*)(g_W + (size_t)(rr + 8) * F + cc) = hi;
        }
    }
}

// ============================================================================
// Main GEMM: out[t, o] = sum_k x[t,k] * W[o,k]   (fp16 inputs, fp32 accum)
// Inline distributed x->fp16 conversion + panel rendezvous (R7/R11 proven).
// CTA tile 128x128, K chunk 64, 3-stage cp.async pipeline, 8 warps (2x4).
// ============================================================================
static constexpr int BM = 128, BN = 128, BK = 64, STAGES = 3;
static constexpr int A_STAGE_BYTES = BM * BK * 2;               // 16384
static constexpr int STAGE_BYTES   = (BM + BN) * BK * 2;        // 32768
static constexpr int SMEM_BYTES    = STAGES * STAGE_BYTES;      // 98304

__global__ __launch_bounds__(256, 2)
void gemm_kernel(const float* __restrict__ x, float* __restrict__ out) {
    extern __shared__ char smem[];
    const uint32_t sbase = smem_to_u32(smem);
    const int tid  = threadIdx.x;
    const int lane = tid & 31, wid = tid >> 5;
    const int m0 = blockIdx.y * BM;
    const int n0 = blockIdx.x * BN;
    const int wm = (wid >> 2) * 64;     // warp m-origin in tile
    const int wn = (wid & 3) * 32;      // warp n-origin in tile

    // ---- distributed conversion: blockIdx.x owns 8 rows of panel m0 ----
    {
        const size_t base = ((size_t)m0 + (size_t)blockIdx.x * 8) * F;
#pragma unroll 8
        for (int it = 0; it < 16; it++) {
            size_t off = base + (size_t)it * 1024 + (size_t)tid * 4;
            float4 v = *(const float4*)(x + off);
            __half2 h0 = __floats2half2_rn(v.x, v.y);
            __half2 h1 = __floats2half2_rn(v.z, v.w);
            uint2 w;
            w.x = *(uint32_t*)&h0; w.y = *(uint32_t*)&h1;
            *(uint2*)(g_X + off) = w;
        }
        __threadfence();
        __syncthreads();
        if (tid == 0) {
            atomicAdd(&g_cnt[blockIdx.y], 1u);
            while (ld_acquire_gpu(&g_cnt[blockIdx.y]) < 16u) { }
        }
        __syncthreads();
    }

    // ---- cp.async geometry: 4 x 16B per thread per operand per stage ----
    uint32_t dst_off[4];
    size_t   srcA[4], srcB[4];
#pragma unroll
    for (int i = 0; i < 4; i++) {
        int u = tid + 256 * i;                // 0..1023
        int row = u >> 3, seg = u & 7;        // 128 rows x 8 segs of 16B
        dst_off[i] = (uint32_t)(row * 128 + ((seg ^ (row & 7)) * 16));
        srcA[i] = (size_t)(m0 + row) * F + seg * 8;
        srcB[i] = (size_t)(n0 + row) * F + seg * 8;
    }
    const __half* gA = g_X;
    const __half* gB = g_W;

    auto issue_stage = [&](int kc, int st) {
        uint32_t sA = sbase + st * STAGE_BYTES;
        uint32_t sB = sA + A_STAGE_BYTES;
        const __half* pa = gA + (size_t)kc * BK;
        const __half* pb = gB + (size_t)kc * BK;
#pragma unroll
        for (int i = 0; i < 4; i++) {
            asm volatile("cp.async.cg.shared.global [%0], [%1], 16;"
                         :: "r"(sA + dst_off[i]), "l"(pa + srcA[i]) : "memory");
            asm volatile("cp.async.cg.shared.global [%0], [%1], 16;"
                         :: "r"(sB + dst_off[i]), "l"(pb + srcB[i]) : "memory");
        }
    };

    // ---- ldmatrix per-lane addressing ----
    const uint32_t aRow = (uint32_t)(wm + (lane & 15));
    const uint32_t bRow = (uint32_t)(wn + ((lane & 7) | ((lane & 16) >> 1)));
    uint32_t xsA[4], xsB[4];
#pragma unroll
    for (int ks = 0; ks < 4; ks++) {
        xsA[ks] = (uint32_t)(((ks * 2 + (lane >> 4)) ^ (lane & 7)) * 16);
        xsB[ks] = (uint32_t)(((ks * 2 + ((lane >> 3) & 1)) ^ (lane & 7)) * 16);
    }
    const uint32_t aBase = aRow * 128u;
    const uint32_t bBase = bRow * 128u;

    float acc[4][4][4];
#pragma unroll
    for (int fm = 0; fm < 4; fm++)
#pragma unroll
        for (int fn = 0; fn < 4; fn++)
#pragma unroll
            for (int k = 0; k < 4; k++) acc[fm][fn][k] = 0.0f;

    auto compute_stage = [&](int st) {
        uint32_t sA = sbase + st * STAGE_BYTES + aBase;
        uint32_t sB = sbase + st * STAGE_BYTES + A_STAGE_BYTES + bBase;
#pragma unroll
        for (int ks = 0; ks < 4; ks++) {
            uint32_t a[4][4], b[8];
#pragma unroll
            for (int fm = 0; fm < 4; fm++) {
                uint32_t addr = sA + (uint32_t)(fm * 2048) + xsA[ks];
                asm volatile(
                    "ldmatrix.sync.aligned.m8n8.x4.shared.b16 {%0,%1,%2,%3}, [%4];"
                    : "=r"(a[fm][0]), "=r"(a[fm][1]), "=r"(a[fm][2]), "=r"(a[fm][3])
                    : "r"(addr));
            }
#pragma unroll
            for (int p = 0; p < 2; p++) {
                uint32_t addr = sB + (uint32_t)(p * 2048) + xsB[ks];
                asm volatile(
                    "ldmatrix.sync.aligned.m8n8.x4.shared.b16 {%0,%1,%2,%3}, [%4];"
                    : "=r"(b[p*4+0]), "=r"(b[p*4+1]), "=r"(b[p*4+2]), "=r"(b[p*4+3])
                    : "r"(addr));
            }
#pragma unroll
            for (int fm = 0; fm < 4; fm++) {
#pragma unroll
                for (int fn = 0; fn < 4; fn++) {
                    uint32_t b0 = b[(fn >> 1) * 4 + (fn & 1) * 2];
                    uint32_t b1 = b[(fn >> 1) * 4 + (fn & 1) * 2 + 1];
                    asm volatile(
                        "mma.sync.aligned.m16n8k16.row.col.f32.f16.f16.f32 "
                        "{%0,%1,%2,%3}, {%4,%5,%6,%7}, {%8,%9}, {%0,%1,%2,%3};"
                        : "+f"(acc[fm][fn][0]), "+f"(acc[fm][fn][1]),
                          "+f"(acc[fm][fn][2]), "+f"(acc[fm][fn][3])
                        : "r"(a[fm][0]), "r"(a[fm][1]), "r"(a[fm][2]), "r"(a[fm][3]),
                          "r"(b0), "r"(b1));
                }
            }
        }
    };

    // ---- pipeline ----
    issue_stage(0, 0);
    asm volatile("cp.async.commit_group;" ::: "memory");
    issue_stage(1, 1);
    asm volatile("cp.async.commit_group;" ::: "memory");

    const int NCHUNK = F / BK;   // 32
    for (int kc = 0; kc < NCHUNK; kc++) {
        asm volatile("cp.async.wait_group 1;" ::: "memory");
        __syncthreads();
        if (kc + 2 < NCHUNK) {
            int nxt = kc + 2;
            issue_stage(nxt, nxt % STAGES);
        }
        asm volatile("cp.async.commit_group;" ::: "memory");
        compute_stage(kc % STAGES);
    }

    // ---- epilogue: direct fp32 stores ----
#pragma unroll
    for (int fm = 0; fm < 4; fm++) {
#pragma unroll
        for (int fn = 0; fn < 4; fn++) {
            int r = m0 + wm + fm * 16 + (lane >> 2);
            int c = n0 + wn + fn * 8 + (lane & 3) * 2;
            float2 v0 = make_float2(acc[fm][fn][0], acc[fm][fn][1]);
            float2 v1 = make_float2(acc[fm][fn][2], acc[fm][fn][3]);
            *(float2*)(out + (size_t)r * F + c)       = v0;
            *(float2*)(out + (size_t)(r + 8) * F + c) = v1;
        }
    }
}

// ============================================================================
// Launch
// ============================================================================
extern "C" void kernel_launch(void* const* d_in, const int* in_sizes, int n_in,
                              void* d_out, int out_size) {
    const float* x      = (const float*)d_in[0];
    const float* stage1 = (const float*)d_in[1];
    const float* stage2 = (const float*)d_in[2];
    const float* mix_w  = (const float*)d_in[3];
    float* out = (float*)d_out;

    cudaFuncSetAttribute(gemm_kernel,
                         cudaFuncAttributeMaxDynamicSharedMemorySize, SMEM_BYTES);

    fold_kernel<<<1024, 256>>>(stage1, stage2, mix_w);
    gemm_kernel<<<dim3(F / BN, TOK / BM), 256, SMEM_BYTES>>>(x, out);
}